// round 2
// baseline (speedup 1.0000x reference)
#include <cuda_runtime.h>
#include <math.h>

// ---------------- config ----------------
#define DTH 384            // threads per block (12 warps/SM, 1 block/SM via smem)

// shared layout (float offsets) — all sections 16B-aligned
#define W1OP   0            // 51*64 = 3264
#define W1COL  3264
#define W1COV  6528
#define W1MOT  9792         // 48*64 = 3072 (temb rows folded into bias)
#define W2OP   12864        // 64*12 (pad 10->12)
#define W2COL  13632        // 64*32 (pad 30->32)
#define W2COV  15680        // 64*72 (pad 70->72)
#define W2MOT  20288        // 64*40 (pad 37->40)
#define B1OP   22848
#define B1COL  22912
#define B1COV  22976
#define BMOT   23040
#define B2OP   23104        // 16 (pad)
#define B2COL  23120        // 32
#define B2COV  23152        // 72
#define B2MOT  23224        // 40
#define TAF    23264        // 51*384 = 19584
#define SMEM_FLOATS (23264 + 51 * DTH)
#define SMEM_BYTES (SMEM_FLOATS * 4)

typedef unsigned long long u64;

__device__ __forceinline__ u64 pack2(float lo, float hi) {
    u64 r; asm("mov.b64 %0,{%1,%2};" : "=l"(r) : "f"(lo), "f"(hi)); return r;
}
__device__ __forceinline__ void unpack2(u64 v, float& lo, float& hi) {
    asm("mov.b64 {%0,%1},%2;" : "=f"(lo), "=f"(hi) : "l"(v));
}
__device__ __forceinline__ void ffma2(u64& d, u64 a, u64 b) {
    asm("fma.rn.f32x2 %0,%1,%2,%0;" : "+l"(d) : "l"(a), "l"(b));
}
__device__ __forceinline__ float sigmoidf_(float x) { return 1.f / (1.f + expf(-x)); }

// layer1: 64 accumulators live in registers (as 32 packed f32x2), h -> registers
__device__ __forceinline__ void layer1(const float* __restrict__ w1,
                                       const float* __restrict__ b1,
                                       int IN,
                                       const float* __restrict__ tafcol,
                                       float* __restrict__ h)
{
    u64 acc[32];
    #pragma unroll
    for (int k = 0; k < 32; k++) acc[k] = *reinterpret_cast<const u64*>(b1 + 2 * k);
    #pragma unroll 1
    for (int i = 0; i < IN; i++) {
        float x = tafcol[i * DTH];
        u64 x2 = pack2(x, x);
        const ulonglong2* wp = reinterpret_cast<const ulonglong2*>(w1 + i * 64);
        #pragma unroll
        for (int q = 0; q < 16; q++) {
            ulonglong2 w = wp[q];
            ffma2(acc[2 * q + 0], x2, w.x);
            ffma2(acc[2 * q + 1], x2, w.y);
        }
    }
    #pragma unroll
    for (int k = 0; k < 32; k++) {
        float a, b; unpack2(acc[k], a, b);
        h[2 * k + 0] = fmaxf(a, 0.f);
        h[2 * k + 1] = fmaxf(b, 0.f);
    }
}

// layer2: h in registers (fully unrolled j), NP u64 accumulators (2*NP outputs)
template <int NP>
__device__ __forceinline__ void layer2(const float* __restrict__ w2, int stride,
                                       int k0, const float* __restrict__ b2,
                                       const float* __restrict__ h,
                                       float* __restrict__ outv)
{
    u64 acc[NP];
    #pragma unroll
    for (int p = 0; p < NP; p++) acc[p] = *reinterpret_cast<const u64*>(b2 + k0 + 2 * p);
    #pragma unroll
    for (int j = 0; j < 64; j++) {
        u64 hj = pack2(h[j], h[j]);
        const ulonglong2* wp = reinterpret_cast<const ulonglong2*>(w2 + j * stride + k0);
        #pragma unroll
        for (int q = 0; q < NP / 2; q++) {
            ulonglong2 w = wp[q];
            ffma2(acc[2 * q + 0], hj, w.x);
            ffma2(acc[2 * q + 1], hj, w.y);
        }
    }
    #pragma unroll
    for (int p = 0; p < NP; p++) unpack2(acc[p], outv[2 * p], outv[2 * p + 1]);
}

__global__ __launch_bounds__(DTH, 1)
void gif_eval_kernel(const float* __restrict__ cam,
                     const float* __restrict__ anchors,
                     const float* __restrict__ scales,
                     const float* __restrict__ afeat,
                     const float* __restrict__ tfeat,
                     const float* __restrict__ factors,
                     const float* __restrict__ op_w1, const float* __restrict__ op_b1,
                     const float* __restrict__ op_w2, const float* __restrict__ op_b2,
                     const float* __restrict__ col_w1, const float* __restrict__ col_b1,
                     const float* __restrict__ col_w2, const float* __restrict__ col_b2,
                     const float* __restrict__ cov_w1, const float* __restrict__ cov_b1,
                     const float* __restrict__ cov_w2, const float* __restrict__ cov_b2,
                     const float* __restrict__ mot_w1, const float* __restrict__ mot_b1,
                     const float* __restrict__ mot_w2, const float* __restrict__ mot_b2,
                     const int* __restrict__ vis,
                     const int* __restrict__ knn,
                     float* __restrict__ out,
                     int M)
{
    extern __shared__ float S[];
    const int tid = threadIdx.x;

    // ---- stage weights into shared ----
    for (int i = tid; i < 3264; i += DTH) {
        S[W1OP  + i] = op_w1[i];
        S[W1COL + i] = col_w1[i];
        S[W1COV + i] = cov_w1[i];
    }
    for (int i = tid; i < 3072; i += DTH) S[W1MOT + i] = mot_w1[i];  // rows 0..47
    for (int i = tid; i < 768; i += DTH) {
        int j = i / 12, k = i - j * 12;
        S[W2OP + i] = (k < 10) ? op_w2[j * 10 + k] : 0.f;
    }
    for (int i = tid; i < 2048; i += DTH) {
        int j = i >> 5, k = i & 31;
        S[W2COL + i] = (k < 30) ? col_w2[j * 30 + k] : 0.f;
    }
    for (int i = tid; i < 4608; i += DTH) {
        int j = i / 72, k = i - j * 72;
        S[W2COV + i] = (k < 70) ? cov_w2[j * 70 + k] : 0.f;
    }
    for (int i = tid; i < 2560; i += DTH) {
        int j = i / 40, k = i - j * 40;
        S[W2MOT + i] = (k < 37) ? mot_w2[j * 37 + k] : 0.f;
    }
    if (tid < 64) {
        S[B1OP  + tid] = op_b1[tid];
        S[B1COL + tid] = col_b1[tid];
        S[B1COV + tid] = cov_b1[tid];
        // fold temb (constant) into motion layer-1 bias
        float acc = mot_b1[tid];
        #pragma unroll
        for (int t = 0; t < 8; t++) {
            float ang = exp2f((float)t) * 1.5707963267948966f;   // 2^t * pi * 0.5
            acc = fmaf(sinf(ang), mot_w1[(48 + t) * 64 + tid], acc);
            acc = fmaf(cosf(ang), mot_w1[(56 + t) * 64 + tid], acc);
        }
        S[BMOT + tid] = acc;
    }
    if (tid < 16) S[B2OP  + tid] = (tid < 10) ? op_b2[tid]  : 0.f;
    if (tid < 32) S[B2COL + tid] = (tid < 30) ? col_b2[tid] : 0.f;
    if (tid < 72) S[B2COV + tid] = (tid < 70) ? cov_b2[tid] : 0.f;
    if (tid < 40) S[B2MOT + tid] = (tid < 37) ? mot_b2[tid] : 0.f;
    __syncthreads();

    const int m = blockIdx.x * DTH + tid;
    if (m >= M) return;

    const int idx = vis[m];
    const float* tafcol = S + TAF + tid;

    // ---- build taf in shared: [feat(32), vdn(3), tf*tff(16)] ----
    const float4* fp = reinterpret_cast<const float4*>(afeat + (long long)idx * 32);
    #pragma unroll
    for (int q = 0; q < 8; q++) {
        float4 v = __ldg(fp + q);
        S[TAF + (4 * q + 0) * DTH + tid] = v.x;
        S[TAF + (4 * q + 1) * DTH + tid] = v.y;
        S[TAF + (4 * q + 2) * DTH + tid] = v.z;
        S[TAF + (4 * q + 3) * DTH + tid] = v.w;
    }
    float ax = __ldg(anchors + (long long)idx * 3 + 0);
    float ay = __ldg(anchors + (long long)idx * 3 + 1);
    float az = __ldg(anchors + (long long)idx * 3 + 2);
    float vx = ax - cam[3], vy = ay - cam[7], vz = az - cam[11];
    float nrm = sqrtf(vx * vx + vy * vy + vz * vz);
    float inv = 1.f / fmaxf(nrm, 1e-8f);
    S[TAF + 32 * DTH + tid] = vx * inv;
    S[TAF + 33 * DTH + tid] = vy * inv;
    S[TAF + 34 * DTH + tid] = vz * inv;

    float4 fc = __ldg(reinterpret_cast<const float4*>(factors + (long long)idx * 4));
    float tff = fc.x, mf = fc.y, kf = fc.z, pf = fc.w;

    const float4* tp = reinterpret_cast<const float4*>(tfeat + (long long)idx * 256 + 112);
    #pragma unroll
    for (int q = 0; q < 4; q++) {
        float4 v = __ldg(tp + q);
        S[TAF + (35 + 4 * q + 0) * DTH + tid] = v.x * tff;
        S[TAF + (35 + 4 * q + 1) * DTH + tid] = v.y * tff;
        S[TAF + (35 + 4 * q + 2) * DTH + tid] = v.z * tff;
        S[TAF + (35 + 4 * q + 3) * DTH + tid] = v.w * tff;
    }

    float* omk = out + (long long)m * 110;
    float h[64];

    // ---- opacity MLP (51->64->10, tanh, *pf) ----
    {
        layer1(S + W1OP, S + B1OP, 51, tafcol, h);
        float ov[12];
        layer2<6>(S + W2OP, 12, 0, S + B2OP, h, ov);
        #pragma unroll
        for (int k = 0; k < 10; k++)
            omk[k * 11] = tanhf(ov[k]) * pf;
    }

    // ---- color MLP (51->64->30, sigmoid) ----
    {
        layer1(S + W1COL, S + B1COL, 51, tafcol, h);
        float ov[32];
        layer2<16>(S + W2COL, 32, 0, S + B2COL, h, ov);
        #pragma unroll
        for (int k = 0; k < 30; k++) {
            int kd = k / 3;
            omk[kd * 11 + 1 + (k - kd * 3)] = sigmoidf_(ov[k]);
        }
    }

    // ---- cov MLP (51->64->70, raw), two passes of 36 ----
    {
        layer1(S + W1COV, S + B1COV, 51, tafcol, h);
        float ov[36];
        layer2<18>(S + W2COV, 72, 0, S + B2COV, h, ov);
        #pragma unroll
        for (int k = 0; k < 36; k++) {
            int kd = k / 7;
            omk[kd * 11 + 4 + (k - kd * 7)] = ov[k];
        }
        layer2<18>(S + W2COV, 72, 36, S + B2COV, h, ov);
        #pragma unroll
        for (int kk = 0; kk < 34; kk++) {
            int k = 36 + kk;
            int kd = k / 7;
            omk[kd * 11 + 4 + (k - kd * 7)] = ov[kk];
        }
    }

    // ---- build taf_ in shared (48 dims), temb folded into bias ----
    {
        float facc[48];
        #pragma unroll
        for (int i = 0; i < 48; i++) facc[i] = 0.f;
        const int* kp = knn + (long long)idx * 6;
        #pragma unroll 1
        for (int nb = 0; nb < 6; nb++) {
            int nidx = __ldg(kp + nb);
            const float4* nf = reinterpret_cast<const float4*>(afeat + (long long)nidx * 32);
            #pragma unroll
            for (int q = 0; q < 8; q++) {
                float4 v = __ldg(nf + q);
                facc[4 * q + 0] += v.x; facc[4 * q + 1] += v.y;
                facc[4 * q + 2] += v.z; facc[4 * q + 3] += v.w;
            }
            const float4* nt = reinterpret_cast<const float4*>(tfeat + (long long)nidx * 256 + 112);
            #pragma unroll
            for (int q = 0; q < 4; q++) {
                float4 v = __ldg(nt + q);
                facc[32 + 4 * q + 0] += v.x; facc[32 + 4 * q + 1] += v.y;
                facc[32 + 4 * q + 2] += v.z; facc[32 + 4 * q + 3] += v.w;
            }
        }
        float wk = (1.f - kf) * (1.f / 6.f);
        #pragma unroll
        for (int i = 0; i < 32; i++)
            S[TAF + i * DTH + tid] = kf * S[TAF + i * DTH + tid] + wk * facc[i];
        #pragma unroll
        for (int c = 0; c < 16; c++)
            S[TAF + (32 + c) * DTH + tid] = kf * S[TAF + (35 + c) * DTH + tid] + wk * facc[32 + c];
    }

    float* om = out + (long long)M * 110 + (long long)m * 50;

    // ---- motion MLP (48->64->37, *mf) ----
    {
        layer1(S + W1MOT, S + BMOT, 48, tafcol, h);
        float ov[40];
        layer2<20>(S + W2MOT, 40, 0, S + B2MOT, h, ov);
        #pragma unroll
        for (int k = 0; k < 37; k++) om[k] = ov[k] * mf;
    }

    // ---- epilogue: scales(exp, last3*pf), factors, anchor ----
    {
        const float* sp = scales + (long long)idx * 6;
        om[37] = expf(__ldg(sp + 0));
        om[38] = expf(__ldg(sp + 1));
        om[39] = expf(__ldg(sp + 2));
        om[40] = expf(__ldg(sp + 3)) * pf;
        om[41] = expf(__ldg(sp + 4)) * pf;
        om[42] = expf(__ldg(sp + 5)) * pf;
        om[43] = tff; om[44] = mf; om[45] = kf; om[46] = pf;
        om[47] = ax; om[48] = ay; om[49] = az;
    }
}

extern "C" void kernel_launch(void* const* d_in, const int* in_sizes, int n_in,
                              void* d_out, int out_size)
{
    const float* cam     = (const float*)d_in[0];
    const float* anchors = (const float*)d_in[1];
    const float* scales  = (const float*)d_in[2];
    const float* afeat   = (const float*)d_in[3];
    const float* tfeat   = (const float*)d_in[4];
    const float* factors = (const float*)d_in[5];
    const float* op_w1   = (const float*)d_in[6];
    const float* op_b1   = (const float*)d_in[7];
    const float* op_w2   = (const float*)d_in[8];
    const float* op_b2   = (const float*)d_in[9];
    const float* col_w1  = (const float*)d_in[10];
    const float* col_b1  = (const float*)d_in[11];
    const float* col_w2  = (const float*)d_in[12];
    const float* col_b2  = (const float*)d_in[13];
    const float* cov_w1  = (const float*)d_in[14];
    const float* cov_b1  = (const float*)d_in[15];
    const float* cov_w2  = (const float*)d_in[16];
    const float* cov_b2  = (const float*)d_in[17];
    const float* mot_w1  = (const float*)d_in[18];
    const float* mot_b1  = (const float*)d_in[19];
    const float* mot_w2  = (const float*)d_in[20];
    const float* mot_b2  = (const float*)d_in[21];
    const int*   vis     = (const int*)d_in[22];
    const int*   knn     = (const int*)d_in[23];

    int M = in_sizes[22];
    float* out = (float*)d_out;

    cudaFuncSetAttribute(gif_eval_kernel,
                         cudaFuncAttributeMaxDynamicSharedMemorySize, SMEM_BYTES);

    int grid = (M + DTH - 1) / DTH;
    gif_eval_kernel<<<grid, DTH, SMEM_BYTES>>>(
        cam, anchors, scales, afeat, tfeat, factors,
        op_w1, op_b1, op_w2, op_b2,
        col_w1, col_b1, col_w2, col_b2,
        cov_w1, cov_b1, cov_w2, cov_b2,
        mot_w1, mot_b1, mot_w2, mot_b2,
        vis, knn, out, M);
}

// round 3
// speedup vs baseline: 1.4453x; 1.4453x over previous
#include <cuda_runtime.h>
#include <math.h>

#define MAXM 400000

// scratch: taf rows [feat32 | vdn3 | tf_scaled16 | pf], taf_ rows [mix48 | mf | pad3]
__device__ float g_taf[(size_t)MAXM * 52];
__device__ float g_tafm[(size_t)MAXM * 52];

typedef unsigned long long u64;

__device__ __forceinline__ u64 pack2(float lo, float hi) {
    u64 r; asm("mov.b64 %0,{%1,%2};" : "=l"(r) : "f"(lo), "f"(hi)); return r;
}
__device__ __forceinline__ void unpack2(u64 v, float& lo, float& hi) {
    asm("mov.b64 {%0,%1},%2;" : "=f"(lo), "=f"(hi) : "l"(v));
}
__device__ __forceinline__ void ffma2(u64& d, u64 a, u64 b) {
    asm("fma.rn.f32x2 %0,%1,%2,%0;" : "+l"(d) : "l"(a), "l"(b));
}
__device__ __forceinline__ float sigmoidf_(float x) { return 1.f / (1.f + expf(-x)); }

// ================= builder: gathers + taf/taf_ + epilogue =================
__global__ __launch_bounds__(256)
void build_kernel(const float* __restrict__ cam,
                  const float* __restrict__ anchors,
                  const float* __restrict__ scales,
                  const float* __restrict__ afeat,
                  const float* __restrict__ tfeat,
                  const float* __restrict__ factors,
                  const int* __restrict__ vis,
                  const int* __restrict__ knn,
                  float* __restrict__ out, int M)
{
    int m = blockIdx.x * 256 + threadIdx.x;
    if (m >= M) return;
    int idx = vis[m];

    float a[52];
    const float4* fp = reinterpret_cast<const float4*>(afeat + (long long)idx * 32);
    #pragma unroll
    for (int q = 0; q < 8; q++) {
        float4 v = __ldg(fp + q);
        a[4*q+0] = v.x; a[4*q+1] = v.y; a[4*q+2] = v.z; a[4*q+3] = v.w;
    }
    float ax = __ldg(anchors + (long long)idx * 3 + 0);
    float ay = __ldg(anchors + (long long)idx * 3 + 1);
    float az = __ldg(anchors + (long long)idx * 3 + 2);
    float vx = ax - cam[3], vy = ay - cam[7], vz = az - cam[11];
    float nrm = sqrtf(vx*vx + vy*vy + vz*vz);
    float inv = 1.f / fmaxf(nrm, 1e-8f);
    a[32] = vx * inv; a[33] = vy * inv; a[34] = vz * inv;

    float4 fc = __ldg(reinterpret_cast<const float4*>(factors + (long long)idx * 4));
    float tff = fc.x, mf = fc.y, kf = fc.z, pf = fc.w;

    const float4* tp = reinterpret_cast<const float4*>(tfeat + (long long)idx * 256 + 112);
    #pragma unroll
    for (int q = 0; q < 4; q++) {
        float4 v = __ldg(tp + q);
        a[35+4*q+0] = v.x*tff; a[35+4*q+1] = v.y*tff;
        a[35+4*q+2] = v.z*tff; a[35+4*q+3] = v.w*tff;
    }
    a[51] = pf;

    float4* tr = reinterpret_cast<float4*>(g_taf + (size_t)m * 52);
    #pragma unroll
    for (int q = 0; q < 13; q++)
        tr[q] = make_float4(a[4*q], a[4*q+1], a[4*q+2], a[4*q+3]);

    // ---- knn mix -> taf_ ----
    float facc[48];
    #pragma unroll
    for (int i = 0; i < 48; i++) facc[i] = 0.f;
    const int* kp = knn + (long long)idx * 6;
    #pragma unroll 1
    for (int nb = 0; nb < 6; nb++) {
        int nidx = __ldg(kp + nb);
        const float4* nf = reinterpret_cast<const float4*>(afeat + (long long)nidx * 32);
        #pragma unroll
        for (int q = 0; q < 8; q++) {
            float4 v = __ldg(nf + q);
            facc[4*q+0] += v.x; facc[4*q+1] += v.y;
            facc[4*q+2] += v.z; facc[4*q+3] += v.w;
        }
        const float4* nt = reinterpret_cast<const float4*>(tfeat + (long long)nidx * 256 + 112);
        #pragma unroll
        for (int q = 0; q < 4; q++) {
            float4 v = __ldg(nt + q);
            facc[32+4*q+0] += v.x; facc[32+4*q+1] += v.y;
            facc[32+4*q+2] += v.z; facc[32+4*q+3] += v.w;
        }
    }
    float wk = (1.f - kf) * (1.f / 6.f);
    float b[52];
    #pragma unroll
    for (int i = 0; i < 32; i++) b[i] = kf * a[i] + wk * facc[i];
    #pragma unroll
    for (int c = 0; c < 16; c++) b[32+c] = kf * a[35+c] + wk * facc[32+c];
    b[48] = mf; b[49] = 0.f; b[50] = 0.f; b[51] = 0.f;

    float4* mr = reinterpret_cast<float4*>(g_tafm + (size_t)m * 52);
    #pragma unroll
    for (int q = 0; q < 13; q++)
        mr[q] = make_float4(b[4*q], b[4*q+1], b[4*q+2], b[4*q+3]);

    // ---- epilogue columns of out_m ----
    float* om = out + (long long)M * 110 + (long long)m * 50;
    const float* sp = scales + (long long)idx * 6;
    om[37] = expf(__ldg(sp + 0));
    om[38] = expf(__ldg(sp + 1));
    om[39] = expf(__ldg(sp + 2));
    om[40] = expf(__ldg(sp + 3)) * pf;
    om[41] = expf(__ldg(sp + 4)) * pf;
    om[42] = expf(__ldg(sp + 5)) * pf;
    om[43] = tff; om[44] = mf; om[45] = kf; om[46] = pf;
    om[47] = ax; om[48] = ay; om[49] = az;
}

// ================= generic small-MLP kernel =================
// smem: [W1: IN*64][W2: 64*W2S][B1: 64][B2: W2S][TAF: 52*256]
// ACT: 0=op(tanh*pf) 1=col(sigmoid) 2=cov(raw) 3=mot(*mf)
template <int IN, int W2S, int NOUT, int NPASS, int ACT>
__global__ __launch_bounds__(256, 2)
void mlp_kernel(const float* __restrict__ tafg,
                const float* __restrict__ w1g, const float* __restrict__ b1g,
                const float* __restrict__ w2g, const float* __restrict__ b2g,
                float* __restrict__ out, int M)
{
    constexpr int NP = W2S / (2 * NPASS);     // u64 accumulators per pass
    constexpr int CH = 2 * NP;                // outputs per pass
    constexpr int OW1 = 0;
    constexpr int OW2 = IN * 64;
    constexpr int OB1 = OW2 + 64 * W2S;
    constexpr int OB2 = OB1 + 64;
    constexpr int OTAF = OB2 + ((W2S + 3) & ~3);

    extern __shared__ float S[];
    const int tid = threadIdx.x;

    for (int i = tid; i < IN * 64; i += 256) S[OW1 + i] = w1g[i];
    for (int i = tid; i < 64 * W2S; i += 256) {
        int j = i / W2S, k = i - j * W2S;
        S[OW2 + i] = (k < NOUT) ? w2g[j * NOUT + k] : 0.f;
    }
    if (tid < 64) {
        float acc = b1g[tid];
        if (ACT == 3) {
            // fold temb into motion layer-1 bias (rows 48..63 of full w1)
            #pragma unroll
            for (int t = 0; t < 8; t++) {
                float ang = exp2f((float)t) * 1.5707963267948966f;
                acc = fmaf(sinf(ang), w1g[(48 + t) * 64 + tid], acc);
                acc = fmaf(cosf(ang), w1g[(56 + t) * 64 + tid], acc);
            }
        }
        S[OB1 + tid] = acc;
    }
    if (tid < W2S) S[OB2 + tid] = (tid < NOUT) ? b2g[tid] : 0.f;
    __syncthreads();

    const int m = blockIdx.x * 256 + tid;
    if (m >= M) return;

    // stage this thread's taf row into TAF columns
    {
        const float4* tr = reinterpret_cast<const float4*>(tafg + (size_t)m * 52);
        #pragma unroll
        for (int q = 0; q < 13; q++) {
            float4 v = __ldg(tr + q);
            S[OTAF + (4*q+0) * 256 + tid] = v.x;
            S[OTAF + (4*q+1) * 256 + tid] = v.y;
            S[OTAF + (4*q+2) * 256 + tid] = v.z;
            S[OTAF + (4*q+3) * 256 + tid] = v.w;
        }
    }

    // ---- layer1 in two 32-neuron chunks, h -> regs ----
    float h[64];
    #pragma unroll 1
    for (int c = 0; c < 2; c++) {
        u64 acc[16];
        #pragma unroll
        for (int k = 0; k < 16; k++)
            acc[k] = *reinterpret_cast<const u64*>(S + OB1 + 32*c + 2*k);
        #pragma unroll 3
        for (int i = 0; i < IN; i++) {
            float x = S[OTAF + i * 256 + tid];
            u64 x2 = pack2(x, x);
            const ulonglong2* wp = reinterpret_cast<const ulonglong2*>(S + OW1 + i * 64 + 32 * c);
            #pragma unroll
            for (int q = 0; q < 8; q++) {
                ulonglong2 w = wp[q];
                ffma2(acc[2*q+0], x2, w.x);
                ffma2(acc[2*q+1], x2, w.y);
            }
        }
        #pragma unroll
        for (int k = 0; k < 16; k++) {
            float lo, hi; unpack2(acc[k], lo, hi);
            h[32*c + 2*k + 0] = fmaxf(lo, 0.f);
            h[32*c + 2*k + 1] = fmaxf(hi, 0.f);
        }
    }

    // ---- layer2 (+ activation/scatter) ----
    #pragma unroll 1
    for (int p = 0; p < NPASS; p++) {
        const int k0 = p * CH;
        u64 acc[NP];
        #pragma unroll
        for (int q = 0; q < NP; q++)
            acc[q] = *reinterpret_cast<const u64*>(S + OB2 + k0 + 2*q);
        #pragma unroll 4
        for (int j = 0; j < 64; j++) {
            u64 hj = pack2(h[j], h[j]);
            const ulonglong2* wp = reinterpret_cast<const ulonglong2*>(S + OW2 + j * W2S + k0);
            #pragma unroll
            for (int q = 0; q < NP / 2; q++) {
                ulonglong2 w = wp[q];
                ffma2(acc[2*q+0], hj, w.x);
                ffma2(acc[2*q+1], hj, w.y);
            }
        }
        float ov[CH];
        #pragma unroll
        for (int q = 0; q < NP; q++) unpack2(acc[q], ov[2*q], ov[2*q+1]);

        if (ACT == 0) {
            float pf = S[OTAF + 51 * 256 + tid];
            float* omk = out + (long long)m * 110;
            #pragma unroll
            for (int k = 0; k < CH; k++)
                if (k < 10) omk[k * 11] = tanhf(ov[k]) * pf;
        } else if (ACT == 1) {
            float* omk = out + (long long)m * 110;
            #pragma unroll
            for (int k = 0; k < CH; k++)
                if (k < 30) {
                    int kd = k / 3;
                    omk[kd * 11 + 1 + (k - kd * 3)] = sigmoidf_(ov[k]);
                }
        } else if (ACT == 2) {
            float* omk = out + (long long)m * 110;
            #pragma unroll
            for (int kk = 0; kk < CH; kk++) {
                int k = k0 + kk;
                if (k < 70) {
                    int kd = k / 7;
                    omk[kd * 11 + 4 + (k - kd * 7)] = ov[kk];
                }
            }
        } else {
            float mf = S[OTAF + 48 * 256 + tid];
            float* om = out + (long long)M * 110 + (long long)m * 50;
            #pragma unroll
            for (int k = 0; k < CH; k++)
                if (k < 37) om[k] = ov[k] * mf;
        }
    }
}

// ================= launch =================
extern "C" void kernel_launch(void* const* d_in, const int* in_sizes, int n_in,
                              void* d_out, int out_size)
{
    const float* cam     = (const float*)d_in[0];
    const float* anchors = (const float*)d_in[1];
    const float* scales  = (const float*)d_in[2];
    const float* afeat   = (const float*)d_in[3];
    const float* tfeat   = (const float*)d_in[4];
    const float* factors = (const float*)d_in[5];
    const float* op_w1   = (const float*)d_in[6];
    const float* op_b1   = (const float*)d_in[7];
    const float* op_w2   = (const float*)d_in[8];
    const float* op_b2   = (const float*)d_in[9];
    const float* col_w1  = (const float*)d_in[10];
    const float* col_b1  = (const float*)d_in[11];
    const float* col_w2  = (const float*)d_in[12];
    const float* col_b2  = (const float*)d_in[13];
    const float* cov_w1  = (const float*)d_in[14];
    const float* cov_b1  = (const float*)d_in[15];
    const float* cov_w2  = (const float*)d_in[16];
    const float* cov_b2  = (const float*)d_in[17];
    const float* mot_w1  = (const float*)d_in[18];
    const float* mot_b1  = (const float*)d_in[19];
    const float* mot_w2  = (const float*)d_in[20];
    const float* mot_b2  = (const float*)d_in[21];
    const int*   vis     = (const int*)d_in[22];
    const int*   knn     = (const int*)d_in[23];

    int M = in_sizes[22];
    float* out = (float*)d_out;

    float* taf;  cudaGetSymbolAddress((void**)&taf,  g_taf);
    float* tafm; cudaGetSymbolAddress((void**)&tafm, g_tafm);

    const int G = (M + 255) / 256;

    // smem bytes per kernel
    auto smem_bytes = [](int IN, int W2S) {
        int f = IN * 64 + 64 * W2S + 64 + ((W2S + 3) & ~3) + 52 * 256;
        return f * 4;
    };
    int smem_op  = smem_bytes(51, 12);
    int smem_col = smem_bytes(51, 32);
    int smem_cov = smem_bytes(51, 72);
    int smem_mot = smem_bytes(48, 40);

    cudaFuncSetAttribute((const void*)mlp_kernel<51,12,10,1,0>, cudaFuncAttributeMaxDynamicSharedMemorySize, smem_op);
    cudaFuncSetAttribute((const void*)mlp_kernel<51,32,30,1,1>, cudaFuncAttributeMaxDynamicSharedMemorySize, smem_col);
    cudaFuncSetAttribute((const void*)mlp_kernel<51,72,70,2,2>, cudaFuncAttributeMaxDynamicSharedMemorySize, smem_cov);
    cudaFuncSetAttribute((const void*)mlp_kernel<48,40,37,1,3>, cudaFuncAttributeMaxDynamicSharedMemorySize, smem_mot);

    build_kernel<<<G, 256>>>(cam, anchors, scales, afeat, tfeat, factors, vis, knn, out, M);
    mlp_kernel<51,12,10,1,0><<<G, 256, smem_op >>>(taf,  op_w1,  op_b1,  op_w2,  op_b2,  out, M);
    mlp_kernel<51,32,30,1,1><<<G, 256, smem_col>>>(taf,  col_w1, col_b1, col_w2, col_b2, out, M);
    mlp_kernel<51,72,70,2,2><<<G, 256, smem_cov>>>(taf,  cov_w1, cov_b1, cov_w2, cov_b2, out, M);
    mlp_kernel<48,40,37,1,3><<<G, 256, smem_mot>>>(tafm, mot_w1, mot_b1, mot_w2, mot_b2, out, M);
}